// round 3
// baseline (speedup 1.0000x reference)
#include <cuda_runtime.h>
#include <math.h>

// Problem constants (fixed by the dataset): predicts/targets (2,4,64,256,256) f32,
// masks (2,1,64,256,256) f32, scalar f32 output.
namespace {
constexpr int Bn = 2, Cn = 4, Dn = 64, Hn = 256, Wn = 256;
constexpr long long CH = (long long)Dn * Hn * Wn;   // one channel volume
}

// Global accumulators (device globals -> no allocation).
__device__ double             g_sum;
__device__ unsigned long long g_cnt;

__global__ void k_zero() {
    g_sum = 0.0;
    g_cnt = 0ull;
}

// One block per interior row (b, z, y). 256 threads cover x = 0..255;
// x in [1, 254] are output voxels.
//
// Key identities used (see analysis):
//  * omega_pred - omega_trgt = vorticity(scale * (P - T)) by linearity
//  * scale (10) cancels with 2*delta (10): omega components are plain
//    neighbor differences of d = P - T per channel.
//  * inclusion & counting condition: all 27 masks in the 3x3x3 neighborhood == 1.
__global__ __launch_bounds__(256, 8)
void k_main(const float* __restrict__ P,
            const float* __restrict__ T,
            const float* __restrict__ M) {
    const int x  = threadIdx.x;            // 0..255
    const int y  = blockIdx.x + 1;         // 1..254
    const int bz = blockIdx.y;             // 0..B*(D-2)-1, z varies fastest within a batch
    const int b  = bz / (Dn - 2);
    const int z  = bz % (Dn - 2) + 1;      // 1..62

    __shared__ float colAnd[Wn];

    // Separable 27-neighborhood test:
    // colAnd[x] = product of 9 mask values (3 z-planes x 3 y-rows) at column x.
    const float* mb = M + (long long)b * CH;
    float prod = 1.f;
    #pragma unroll
    for (int dz = -1; dz <= 1; ++dz) {
        const float* plane = mb + (long long)(z + dz) * Hn * Wn;
        #pragma unroll
        for (int dy = -1; dy <= 1; ++dy)
            prod *= plane[(y + dy) * Wn + x];
    }
    colAnd[x] = prod;
    __syncthreads();

    float s = 0.f;
    int   c = 0;
    if (x >= 1 && x <= Wn - 2) {
        // all 27 == 1  <=>  ok > 0 (masks are exactly 0.0 / 1.0)
        const float ok = colAnd[x - 1] * colAnd[x] * colAnd[x + 1];
        if (ok > 0.f) {
            c = 1;
            const float* Pu = P + ((long long)b * Cn + 1) * CH;
            const float* Tu = T + ((long long)b * Cn + 1) * CH;
            const float* Pv = Pu + CH;  const float* Tv = Tu + CH;
            const float* Pw = Pv + CH;  const float* Tw = Tv + CH;

            const long long i  = ((long long)z * Hn + y) * Wn + x;
            const long long zp = i + (long long)Hn * Wn;
            const long long zm = i - (long long)Hn * Wn;
            const long long yp = i + Wn;
            const long long ym = i - Wn;

            // d = P - T per channel; scaling cancels (10 / (2*5) = 1).
            const float ox = ((Pw[yp] - Tw[yp]) - (Pw[ym] - Tw[ym]))
                           - ((Pv[zp] - Tv[zp]) - (Pv[zm] - Tv[zm]));
            const float oy = ((Pu[zp] - Tu[zp]) - (Pu[zm] - Tu[zm]))
                           - ((Pw[i + 1] - Tw[i + 1]) - (Pw[i - 1] - Tw[i - 1]));
            const float oz = ((Pv[i + 1] - Tv[i + 1]) - (Pv[i - 1] - Tv[i - 1]))
                           - ((Pu[yp] - Tu[yp]) - (Pu[ym] - Tu[ym]));

            const float sq = ox * ox + oy * oy + oz * oz;
            s = (sq > 0.f) ? sqrtf(sq) : 0.f;   // safe-norm (sqrt(0)=0 anyway)
        }
    }

    // Block reduction: warp shuffle, then cross-warp via shared, one atomic per block.
    #pragma unroll
    for (int off = 16; off; off >>= 1) {
        s += __shfl_down_sync(0xffffffffu, s, off);
        c += __shfl_down_sync(0xffffffffu, c, off);
    }
    __shared__ float wsum[8];
    __shared__ int   wcnt[8];
    const int wid = threadIdx.x >> 5;
    const int lid = threadIdx.x & 31;
    if (lid == 0) { wsum[wid] = s; wcnt[wid] = c; }
    __syncthreads();
    if (wid == 0) {
        s = (lid < 8) ? wsum[lid] : 0.f;
        c = (lid < 8) ? wcnt[lid] : 0;
        #pragma unroll
        for (int off = 4; off; off >>= 1) {
            s += __shfl_down_sync(0xffffffffu, s, off);
            c += __shfl_down_sync(0xffffffffu, c, off);
        }
        if (lid == 0 && c > 0) {
            atomicAdd(&g_sum, (double)s);
            atomicAdd(&g_cnt, (unsigned long long)c);
        }
    }
}

__global__ void k_final(float* __restrict__ out) {
    out[0] = (float)(g_sum / (double)g_cnt);
}

extern "C" void kernel_launch(void* const* d_in, const int* in_sizes, int n_in,
                              void* d_out, int out_size) {
    const float* P = (const float*)d_in[0];   // predicts
    const float* T = (const float*)d_in[1];   // targets
    const float* M = (const float*)d_in[2];   // masks
    float*       O = (float*)d_out;

    k_zero<<<1, 1>>>();
    dim3 grid(Hn - 2, Bn * (Dn - 2));         // y fast-varying -> z-slab L2 reuse
    k_main<<<grid, 256>>>(P, T, M);
    k_final<<<1, 1>>>(O);
}